// round 15
// baseline (speedup 1.0000x reference)
#include <cuda_runtime.h>
#include <cuda_bf16.h>
#include <stdint.h>

// Problem constants (fixed by the reference setup)
#define N_BATCH 8
#define C_CH    490     // OUTPUT_DIM * GROUP * GROUP = 10*49
#define H_DIM   64
#define W_DIM   64
#define R_ROIS  2000
#define D_OUT   10
#define G_GRP   7
#define G2_CNT  49      // 7*7
#define SPATIAL_SCALE 0.0625f

// Integral storage per plane: S[r][c] = integral(r, c+1) for r=0..64, c=0..63
// (row 0 = zeros; integral column 0 handled by a branchless select in pooling)
#define S_STRIDE 68     // even stride: float2 STS 8B-bank = (34r + lane)%32, conflict-free
#define S_ROWS   65
#define PLANE_SF (S_ROWS * S_STRIDE)    // 4420 floats = 17.68 KB
#define WPB      2                      // warps (planes) per block -> 35.4 KB static smem

// Small scratch (L2-resident): packed bin bounds per (roi, g2), batch buckets.
__device__ uint32_t g_bounds[R_ROIS * G2_CNT];   // 392 KB
__device__ int      g_roi_sorted[R_ROIS];
__device__ int      g_batch_start[N_BATCH + 1];

// ---------------------------------------------------------------------------
// Prep (single launch): block 0 buckets ROIs by batch; other blocks compute
// packed bin bounds, concurrently.
// Bounds math: EXACT chain validated R8-R14 (bit-critical, DO NOT TOUCH):
//   bh = roi_h * fl(1/7)  (reciprocal multiply, XLA-style)
//   boundaries = SEPARATE __fmul_rn + __fadd_rn (no FMA contraction)
// ---------------------------------------------------------------------------
__global__ void __launch_bounds__(256) prep_kernel(const float* __restrict__ rois) {
    const int tid = threadIdx.x;

    if (blockIdx.x == 0) {
        __shared__ int counts[N_BATCH];
        __shared__ int cursor[N_BATCH];
        if (tid < N_BATCH) counts[tid] = 0;
        __syncthreads();
        for (int i = tid; i < R_ROIS; i += 256) {
            int b = (int)rois[i * 5];
            atomicAdd(&counts[b], 1);
        }
        __syncthreads();
        if (tid == 0) {
            int acc = 0;
            for (int n = 0; n < N_BATCH; ++n) {
                g_batch_start[n] = acc;
                cursor[n] = acc;
                acc += counts[n];
            }
            g_batch_start[N_BATCH] = acc;
        }
        __syncthreads();
        for (int i = tid; i < R_ROIS; i += 256) {
            int b = (int)rois[i * 5];
            int pos = atomicAdd(&cursor[b], 1);
            g_roi_sorted[pos] = i;
        }
        return;
    }

    const int idx = (blockIdx.x - 1) * 256 + tid;
    if (idx >= R_ROIS * G2_CNT) return;

    const int r  = idx / G2_CNT;
    const int g2 = idx - r * G2_CNT;
    const int gh = g2 / G_GRP;
    const int gw = g2 - gh * G_GRP;

    const float* roi = rois + r * 5;

    const float rsw = __fmul_rn(rintf(roi[1]), SPATIAL_SCALE);
    const float rsh = __fmul_rn(rintf(roi[2]), SPATIAL_SCALE);
    const float rew = __fmul_rn(rintf(__fadd_rn(roi[3], 1.0f)), SPATIAL_SCALE);
    const float reh = __fmul_rn(rintf(__fadd_rn(roi[4], 1.0f)), SPATIAL_SCALE);

    const float roi_w = fmaxf(__fsub_rn(rew, rsw), 0.1f);
    const float roi_h = fmaxf(__fsub_rn(reh, rsh), 0.1f);

    const float INV7 = 1.0f / 7.0f;                  // fl(1/7), compile-time rn
    const float bw = __fmul_rn(roi_w, INV7);
    const float bh = __fmul_rn(roi_h, INV7);

    const float ghf  = (float)gh,  gwf  = (float)gw;
    const float gh1f = ghf + 1.0f, gw1f = gwf + 1.0f;

    float hs_f = floorf(__fadd_rn(rsh, __fmul_rn(ghf,  bh)));
    float he_f = ceilf (__fadd_rn(rsh, __fmul_rn(gh1f, bh)));
    float ws_f = floorf(__fadd_rn(rsw, __fmul_rn(gwf,  bw)));
    float we_f = ceilf (__fadd_rn(rsw, __fmul_rn(gw1f, bw)));

    hs_f = fminf(fmaxf(hs_f, 0.f), (float)H_DIM);
    he_f = fminf(fmaxf(he_f, 0.f), (float)H_DIM);
    ws_f = fminf(fmaxf(ws_f, 0.f), (float)W_DIM);
    we_f = fminf(fmaxf(we_f, 0.f), (float)W_DIM);

    g_bounds[idx] = (uint32_t)(int)hs_f
                  | ((uint32_t)(int)he_f << 8)
                  | ((uint32_t)(int)ws_f << 16)
                  | ((uint32_t)(int)we_f << 24);
}

// ---------------------------------------------------------------------------
// Fused kernel, WARP-AUTONOMOUS: one warp owns one (n,c) plane end-to-end.
// No __syncthreads anywhere. Per feature row:
//   coalesced float2 LDG -> register Kogge-Stone row scan (5 shfl)
//   -> register column accumulators (H cumsum) -> one conflict-free STS.64.
// Raw tile and intermediate scan never touch smem (~5k smem lane-ops/plane
// vs ~27k in the barrier-phased versions R10-R14).
// Sum association reassociated (validated R13/R14: rel_err ~2e-6).
// ---------------------------------------------------------------------------
__global__ void __launch_bounds__(WPB * 32) fused_kernel(const float* __restrict__ feature,
                                                         float* __restrict__ out) {
    __shared__ float S[WPB * PLANE_SF];

    const int wslot = threadIdx.x >> 5;
    const int lane  = threadIdx.x & 31;
    const int plane = blockIdx.x * WPB + wslot;   // 0 .. 3919
    const int n  = plane / C_CH;
    const int c  = plane - n * C_CH;
    const int g2 = c % G2_CNT;

    float* __restrict__ Sp = S + wslot * PLANE_SF;
    const float* __restrict__ src = feature + (size_t)plane * (H_DIM * W_DIM);

    // Row 0 of the integral = zeros (only cols 0..63 are ever read)
    Sp[lane] = 0.f;
    Sp[lane + 32] = 0.f;

    // Column accumulators for feature cols 2*lane, 2*lane+1
    float accx = 0.f, accy = 0.f;

    #pragma unroll 8
    for (int r = 0; r < H_DIM; ++r) {
        const float2 v = *(const float2*)(src + r * W_DIM + 2 * lane);

        // Kogge-Stone inclusive scan of pair sums across the warp
        const float pair = v.x + v.y;
        float inc = pair;
        #pragma unroll
        for (int d = 1; d < 32; d <<= 1) {
            const float up = __shfl_up_sync(0xFFFFFFFFu, inc, d);
            if (lane >= d) inc += up;
        }
        const float excl = inc - pair;
        const float o1 = excl + v.x;      // row-scan value at col 2*lane
        const float o2 = o1 + v.y;        // row-scan value at col 2*lane+1

        // H cumsum (only cross-row dependency: 2 adds)
        accx += o1;
        accy += o2;

        // Integral row r+1: S[r+1][2l] = integral(r+1, 2l+1), S[r+1][2l+1] = integral(r+1, 2l+2)
        *(float2*)(Sp + (r + 1) * S_STRIDE + 2 * lane) = make_float2(accx, accy);
    }
    __syncwarp();

    // Pooling: this warp serves out[r*490 + c] for every ROI r of batch n.
    const int s_idx = g_batch_start[n];
    const int e_idx = g_batch_start[n + 1];

    for (int i = s_idx + lane; i < e_idx; i += 32) {
        const int rr = g_roi_sorted[i];
        const uint32_t pk = g_bounds[rr * G2_CNT + g2];
        const int hs = (int)(pk & 0xFF);
        const int he = (int)((pk >> 8) & 0xFF);
        const int ws = (int)((pk >> 16) & 0xFF);
        const int we = (int)(pk >> 24);

        // integral(row, col): col==0 -> 0, else Sp[row*S_STRIDE + col-1]
        const float b00 = (we == 0) ? 0.f : Sp[he * S_STRIDE + (we - 1)];
        const float b01 = (we == 0) ? 0.f : Sp[hs * S_STRIDE + (we - 1)];
        const float b10 = (ws == 0) ? 0.f : Sp[he * S_STRIDE + (ws - 1)];
        const float b11 = (ws == 0) ? 0.f : Sp[hs * S_STRIDE + (ws - 1)];

        const float sum = ((b00 - b01) - b10) + b11;

        const int area = (he - hs) * (we - ws);
        const float inv_area = 1.0f / fmaxf((float)area, 1.0f);
        out[(size_t)rr * C_CH + c] = (area <= 0) ? 0.f : sum * inv_area;
    }
}

extern "C" void kernel_launch(void* const* d_in, const int* in_sizes, int n_in,
                              void* d_out, int out_size) {
    const float* feature = (const float*)d_in[0];   // (8, 490, 64, 64) fp32
    const float* rois    = (const float*)d_in[1];   // (2000, 5) fp32
    float* out = (float*)d_out;                     // (2000, 10, 7, 7) fp32

    const int bounds_blocks = (R_ROIS * G2_CNT + 255) / 256;   // 383
    prep_kernel<<<1 + bounds_blocks, 256>>>(rois);
    fused_kernel<<<(N_BATCH * C_CH) / WPB, WPB * 32>>>(feature, out);
}

// round 16
// speedup vs baseline: 1.3367x; 1.3367x over previous
#include <cuda_runtime.h>
#include <cuda_bf16.h>
#include <stdint.h>

// Problem constants (fixed by the reference setup)
#define N_BATCH 8
#define C_CH    490     // OUTPUT_DIM * GROUP * GROUP = 10*49
#define H_DIM   64
#define W_DIM   64
#define R_ROIS  2000
#define D_OUT   10
#define G_GRP   7
#define G2_CNT  49      // 7*7
#define SPATIAL_SCALE 0.0625f

// Integral layout per plane: S[r][c] = integral(r, c+1), r = 0..64, c = 0..63.
// Row 0 = zeros; integral col 0 = 0 handled by branchless select in pooling
// (validated R15). Stride 68 = 4*17: rows 16B-aligned; all access patterns
// below are bank-conflict-free (float4 row-walk phases cover distinct banks).
#define S_STRIDE 68
#define S_ROWS   65
#define PLANE_SF (S_ROWS * S_STRIDE)    // 4420 floats = 17.68 KB

// Small scratch (L2-resident): packed bin bounds per (roi, g2), batch buckets.
__device__ uint32_t g_bounds[R_ROIS * G2_CNT];   // 392 KB
__device__ int      g_roi_sorted[R_ROIS];
__device__ int      g_batch_start[N_BATCH + 1];

// ---------------------------------------------------------------------------
// Prep (single launch): block 0 buckets ROIs by batch; other blocks compute
// packed bin bounds, concurrently.
// Bounds math: EXACT chain validated R8-R15 (bit-critical, DO NOT TOUCH):
//   bh = roi_h * fl(1/7)  (reciprocal multiply, XLA-style)
//   boundaries = SEPARATE __fmul_rn + __fadd_rn (no FMA contraction)
// ---------------------------------------------------------------------------
__global__ void __launch_bounds__(256) prep_kernel(const float* __restrict__ rois) {
    const int tid = threadIdx.x;

    if (blockIdx.x == 0) {
        __shared__ int counts[N_BATCH];
        __shared__ int cursor[N_BATCH];
        if (tid < N_BATCH) counts[tid] = 0;
        __syncthreads();
        for (int i = tid; i < R_ROIS; i += 256) {
            int b = (int)rois[i * 5];
            atomicAdd(&counts[b], 1);
        }
        __syncthreads();
        if (tid == 0) {
            int acc = 0;
            for (int n = 0; n < N_BATCH; ++n) {
                g_batch_start[n] = acc;
                cursor[n] = acc;
                acc += counts[n];
            }
            g_batch_start[N_BATCH] = acc;
        }
        __syncthreads();
        for (int i = tid; i < R_ROIS; i += 256) {
            int b = (int)rois[i * 5];
            int pos = atomicAdd(&cursor[b], 1);
            g_roi_sorted[pos] = i;
        }
        return;
    }

    const int idx = (blockIdx.x - 1) * 256 + tid;
    if (idx >= R_ROIS * G2_CNT) return;

    const int r  = idx / G2_CNT;
    const int g2 = idx - r * G2_CNT;
    const int gh = g2 / G_GRP;
    const int gw = g2 - gh * G_GRP;

    const float* roi = rois + r * 5;

    const float rsw = __fmul_rn(rintf(roi[1]), SPATIAL_SCALE);
    const float rsh = __fmul_rn(rintf(roi[2]), SPATIAL_SCALE);
    const float rew = __fmul_rn(rintf(__fadd_rn(roi[3], 1.0f)), SPATIAL_SCALE);
    const float reh = __fmul_rn(rintf(__fadd_rn(roi[4], 1.0f)), SPATIAL_SCALE);

    const float roi_w = fmaxf(__fsub_rn(rew, rsw), 0.1f);
    const float roi_h = fmaxf(__fsub_rn(reh, rsh), 0.1f);

    const float INV7 = 1.0f / 7.0f;                  // fl(1/7), compile-time rn
    const float bw = __fmul_rn(roi_w, INV7);
    const float bh = __fmul_rn(roi_h, INV7);

    const float ghf  = (float)gh,  gwf  = (float)gw;
    const float gh1f = ghf + 1.0f, gw1f = gwf + 1.0f;

    float hs_f = floorf(__fadd_rn(rsh, __fmul_rn(ghf,  bh)));
    float he_f = ceilf (__fadd_rn(rsh, __fmul_rn(gh1f, bh)));
    float ws_f = floorf(__fadd_rn(rsw, __fmul_rn(gwf,  bw)));
    float we_f = ceilf (__fadd_rn(rsw, __fmul_rn(gw1f, bw)));

    hs_f = fminf(fmaxf(hs_f, 0.f), (float)H_DIM);
    he_f = fminf(fmaxf(he_f, 0.f), (float)H_DIM);
    ws_f = fminf(fmaxf(ws_f, 0.f), (float)W_DIM);
    we_f = fminf(fmaxf(we_f, 0.f), (float)W_DIM);

    g_bounds[idx] = (uint32_t)(int)hs_f
                  | ((uint32_t)(int)he_f << 8)
                  | ((uint32_t)(int)ws_f << 16)
                  | ((uint32_t)(int)we_f << 24);
}

// ---------------------------------------------------------------------------
// Fused kernel: R10's winning structure (2 planes / d-pair / shared g2 per
// 128-thread block, 64 threads per plane, full-length serial scans) with the
// instruction diet: no left pad, stride 68, float4 W-cumsum (16 LDS.128
// instead of 64 scalar LDS per row), branchless col-0 selects in pooling.
// ---------------------------------------------------------------------------
__global__ void __launch_bounds__(128) fused_kernel(const float* __restrict__ feature,
                                                    float* __restrict__ out) {
    __shared__ float S[2 * PLANE_SF];             // 35.36 KB -> 6 blocks/SM

    const int bid = blockIdx.x;                   // 0 .. 1959
    const int n   = bid / (G2_CNT * (D_OUT / 2));
    const int rem = bid - n * (G2_CNT * (D_OUT / 2));
    const int g2  = rem / (D_OUT / 2);
    const int k   = rem - g2 * (D_OUT / 2);       // 0..4
    const int c1  = (2 * k) * G2_CNT + g2;
    const int c2  = c1 + G2_CNT;

    const int tid  = threadIdx.x;
    const int half = tid >> 6;                    // 0: plane A (c1), 1: plane B (c2)
    const int t    = tid & 63;

    float* __restrict__ Sp = S + half * PLANE_SF;
    const int my_c = half ? c2 : c1;
    const float* __restrict__ src =
        feature + ((size_t)(n * C_CH + my_c)) * (H_DIM * W_DIM);

    // Row 0 of the integral = zeros (cols 0..63)
    Sp[t] = 0.f;

    // Interior load: 1024 float4 per plane over 64 threads (16 iterations).
    // STS.128 at 16B-aligned addrs ((row+1)*68 + col0, both mult of 4).
    {
        const float4* __restrict__ src4 = (const float4*)src;
        #pragma unroll
        for (int i = t; i < (H_DIM * W_DIM) / 4; i += 64) {
            const float4 v = src4[i];
            const int row  = i >> 4;              // (i*4)/64
            const int col0 = (i & 15) << 2;       // (i*4)%64
            *(float4*)(Sp + (row + 1) * S_STRIDE + col0) = v;
        }
    }
    __syncthreads();

    // Pass 1: cumsum along H. Thread t owns col-offset t (integral col t+1).
    // Consecutive t -> consecutive banks: conflict-free. Pointer-marched.
    {
        float s = 0.f;
        float* p = Sp + S_STRIDE + t;             // row 1
        #pragma unroll
        for (int r = 0; r < H_DIM; ++r) {
            s += *p;
            *p = s;
            p += S_STRIDE;
        }
    }
    __syncthreads();

    // Pass 2: cumsum along W via float4. Thread t owns row t+1.
    // LDS.128 phase (8 lanes, rows r..r+7): banks 4r mod 32 distinct -> clean.
    {
        float4* rp4 = (float4*)(Sp + (t + 1) * S_STRIDE);
        float s = 0.f;
        #pragma unroll
        for (int q = 0; q < 16; ++q) {
            float4 v = rp4[q];
            s += v.x; v.x = s;
            s += v.y; v.y = s;
            s += v.z; v.z = s;
            s += v.w; v.w = s;
            rp4[q] = v;
        }
    }
    __syncthreads();

    // Pooling: all 128 threads; one bounds load serves both planes.
    // integral(row, col) = (col == 0) ? 0 : S[row*68 + col-1]  (row 0 stored).
    const float* __restrict__ A = S;
    const float* __restrict__ B = S + PLANE_SF;
    const int s_idx = g_batch_start[n];
    const int e_idx = g_batch_start[n + 1];

    for (int i = s_idx + tid; i < e_idx; i += 128) {
        const int rr = g_roi_sorted[i];
        const uint32_t pk = g_bounds[rr * G2_CNT + g2];
        const int hs = (int)(pk & 0xFF);
        const int he = (int)((pk >> 8) & 0xFF);
        const int ws = (int)((pk >> 16) & 0xFF);
        const int we = (int)(pk >> 24);

        const int oe  = we - 1;                   // col offset for we
        const int os  = ws - 1;                   // col offset for ws
        const bool zwe = (we == 0);
        const bool zws = (ws == 0);

        const float a00 = zwe ? 0.f : A[he * S_STRIDE + oe];
        const float a01 = zwe ? 0.f : A[hs * S_STRIDE + oe];
        const float a10 = zws ? 0.f : A[he * S_STRIDE + os];
        const float a11 = zws ? 0.f : A[hs * S_STRIDE + os];

        const float b00 = zwe ? 0.f : B[he * S_STRIDE + oe];
        const float b01 = zwe ? 0.f : B[hs * S_STRIDE + oe];
        const float b10 = zws ? 0.f : B[he * S_STRIDE + os];
        const float b11 = zws ? 0.f : B[hs * S_STRIDE + os];

        const float sA = ((a00 - a01) - a10) + a11;
        const float sB = ((b00 - b01) - b10) + b11;

        const int area = (he - hs) * (we - ws);
        const float inv_area = 1.0f / fmaxf((float)area, 1.0f);
        const bool empty = (area <= 0);

        float* op = out + (size_t)rr * C_CH;
        op[c1] = empty ? 0.f : sA * inv_area;
        op[c2] = empty ? 0.f : sB * inv_area;
    }
}

extern "C" void kernel_launch(void* const* d_in, const int* in_sizes, int n_in,
                              void* d_out, int out_size) {
    const float* feature = (const float*)d_in[0];   // (8, 490, 64, 64) fp32
    const float* rois    = (const float*)d_in[1];   // (2000, 5) fp32
    float* out = (float*)d_out;                     // (2000, 10, 7, 7) fp32

    const int bounds_blocks = (R_ROIS * G2_CNT + 255) / 256;   // 383
    prep_kernel<<<1 + bounds_blocks, 256>>>(rois);
    fused_kernel<<<N_BATCH * G2_CNT * (D_OUT / 2), 128>>>(feature, out);
}

// round 17
// speedup vs baseline: 1.4481x; 1.0833x over previous
#include <cuda_runtime.h>
#include <cuda_bf16.h>
#include <stdint.h>

// Problem constants (fixed by the reference setup)
#define N_BATCH 8
#define C_CH    490     // OUTPUT_DIM * GROUP * GROUP = 10*49
#define H_DIM   64
#define W_DIM   64
#define R_ROIS  2000
#define D_OUT   10
#define G_GRP   7
#define G2_CNT  49      // 7*7
#define SPATIAL_SCALE 0.0625f

// Integral layout per plane: S[r][c] = integral(r, c+1), r = 0..64, c = 0..63.
// Row 0 = zeros; integral col 0 = 0 via branchless select in pooling
// (validated R15/R16). Stride 68 = 4*17: rows 16B-aligned, float4 row walks
// bank-conflict-free.
#define S_STRIDE 68
#define S_ROWS   65
#define PLANE_SF (S_ROWS * S_STRIDE)    // 4420 floats = 17.68 KB

// Small scratch (L2-resident): packed bin bounds per (roi, g2), batch buckets.
__device__ uint32_t g_bounds[R_ROIS * G2_CNT];   // 392 KB
__device__ int      g_roi_sorted[R_ROIS];
__device__ int      g_batch_start[N_BATCH + 1];

// ---------------------------------------------------------------------------
// Prep (single launch): block 0 buckets ROIs by batch; other blocks compute
// packed bin bounds, concurrently.
// Bounds math: EXACT chain validated R8-R16 (bit-critical, DO NOT TOUCH):
//   bh = roi_h * fl(1/7)  (reciprocal multiply, XLA-style)
//   boundaries = SEPARATE __fmul_rn + __fadd_rn (no FMA contraction)
// ---------------------------------------------------------------------------
__global__ void __launch_bounds__(256) prep_kernel(const float* __restrict__ rois) {
    const int tid = threadIdx.x;

    if (blockIdx.x == 0) {
        __shared__ int counts[N_BATCH];
        __shared__ int cursor[N_BATCH];
        if (tid < N_BATCH) counts[tid] = 0;
        __syncthreads();
        for (int i = tid; i < R_ROIS; i += 256) {
            int b = (int)rois[i * 5];
            atomicAdd(&counts[b], 1);
        }
        __syncthreads();
        if (tid == 0) {
            int acc = 0;
            for (int n = 0; n < N_BATCH; ++n) {
                g_batch_start[n] = acc;
                cursor[n] = acc;
                acc += counts[n];
            }
            g_batch_start[N_BATCH] = acc;
        }
        __syncthreads();
        for (int i = tid; i < R_ROIS; i += 256) {
            int b = (int)rois[i * 5];
            int pos = atomicAdd(&cursor[b], 1);
            g_roi_sorted[pos] = i;
        }
        return;
    }

    const int idx = (blockIdx.x - 1) * 256 + tid;
    if (idx >= R_ROIS * G2_CNT) return;

    const int r  = idx / G2_CNT;
    const int g2 = idx - r * G2_CNT;
    const int gh = g2 / G_GRP;
    const int gw = g2 - gh * G_GRP;

    const float* roi = rois + r * 5;

    const float rsw = __fmul_rn(rintf(roi[1]), SPATIAL_SCALE);
    const float rsh = __fmul_rn(rintf(roi[2]), SPATIAL_SCALE);
    const float rew = __fmul_rn(rintf(__fadd_rn(roi[3], 1.0f)), SPATIAL_SCALE);
    const float reh = __fmul_rn(rintf(__fadd_rn(roi[4], 1.0f)), SPATIAL_SCALE);

    const float roi_w = fmaxf(__fsub_rn(rew, rsw), 0.1f);
    const float roi_h = fmaxf(__fsub_rn(reh, rsh), 0.1f);

    const float INV7 = 1.0f / 7.0f;                  // fl(1/7), compile-time rn
    const float bw = __fmul_rn(roi_w, INV7);
    const float bh = __fmul_rn(roi_h, INV7);

    const float ghf  = (float)gh,  gwf  = (float)gw;
    const float gh1f = ghf + 1.0f, gw1f = gwf + 1.0f;

    float hs_f = floorf(__fadd_rn(rsh, __fmul_rn(ghf,  bh)));
    float he_f = ceilf (__fadd_rn(rsh, __fmul_rn(gh1f, bh)));
    float ws_f = floorf(__fadd_rn(rsw, __fmul_rn(gwf,  bw)));
    float we_f = ceilf (__fadd_rn(rsw, __fmul_rn(gw1f, bw)));

    hs_f = fminf(fmaxf(hs_f, 0.f), (float)H_DIM);
    he_f = fminf(fmaxf(he_f, 0.f), (float)H_DIM);
    ws_f = fminf(fmaxf(ws_f, 0.f), (float)W_DIM);
    we_f = fminf(fmaxf(we_f, 0.f), (float)W_DIM);

    g_bounds[idx] = (uint32_t)(int)hs_f
                  | ((uint32_t)(int)he_f << 8)
                  | ((uint32_t)(int)ws_f << 16)
                  | ((uint32_t)(int)we_f << 24);
}

// ---------------------------------------------------------------------------
// Fused kernel: 2 planes (d-pair, shared g2 bounds) per 128-thread block.
// KEY CHANGE vs R16: the global load IS pass 1. Thread t owns feature
// column t; iterating rows gives perfectly coalesced LDG per warp, and the
// H-cumsum lives in a register. The staging STS/LDS round trip and the
// load-phase barrier are gone - DRAM latency overlaps the FADD chain for
// the entire pass.
// ---------------------------------------------------------------------------
__global__ void __launch_bounds__(128) fused_kernel(const float* __restrict__ feature,
                                                    float* __restrict__ out) {
    __shared__ float S[2 * PLANE_SF];             // 35.36 KB -> 6 blocks/SM

    const int bid = blockIdx.x;                   // 0 .. 1959
    const int n   = bid / (G2_CNT * (D_OUT / 2));
    const int rem = bid - n * (G2_CNT * (D_OUT / 2));
    const int g2  = rem / (D_OUT / 2);
    const int k   = rem - g2 * (D_OUT / 2);       // 0..4
    const int c1  = (2 * k) * G2_CNT + g2;
    const int c2  = c1 + G2_CNT;

    const int tid  = threadIdx.x;
    const int half = tid >> 6;                    // 0: plane A (c1), 1: plane B (c2)
    const int t    = tid & 63;

    float* __restrict__ Sp = S + half * PLANE_SF;
    const int my_c = half ? c2 : c1;
    const float* __restrict__ src =
        feature + ((size_t)(n * C_CH + my_c)) * (H_DIM * W_DIM);

    // Row 0 of the integral = zeros (cols 0..63)
    Sp[t] = 0.f;

    // Fused load + pass 1 (H cumsum): thread t owns feature column t.
    // LDG addresses are independent of the accumulator -> deep MLP; the
    // dependent chain is 64 FADDs. STS stride 68, consecutive t: clean.
    {
        const float* __restrict__ p = src + t;
        float* __restrict__ q = Sp + S_STRIDE + t;
        float acc = 0.f;
        #pragma unroll
        for (int r = 0; r < H_DIM; ++r) {
            acc += p[r * W_DIM];
            q[r * S_STRIDE] = acc;
        }
    }
    __syncthreads();

    // Pass 2: cumsum along W via float4. Thread t owns integral row t+1.
    // LDS.128 8-lane phases hit banks 4r mod 32: distinct -> conflict-free.
    {
        float4* rp4 = (float4*)(Sp + (t + 1) * S_STRIDE);
        float s = 0.f;
        #pragma unroll
        for (int q = 0; q < 16; ++q) {
            float4 v = rp4[q];
            s += v.x; v.x = s;
            s += v.y; v.y = s;
            s += v.z; v.z = s;
            s += v.w; v.w = s;
            rp4[q] = v;
        }
    }
    __syncthreads();

    // Pooling: all 128 threads; one bounds load serves both planes.
    // integral(row, col) = (col == 0) ? 0 : S[row*68 + col-1]  (row 0 stored).
    const float* __restrict__ A = S;
    const float* __restrict__ B = S + PLANE_SF;
    const int s_idx = g_batch_start[n];
    const int e_idx = g_batch_start[n + 1];

    for (int i = s_idx + tid; i < e_idx; i += 128) {
        const int rr = g_roi_sorted[i];
        const uint32_t pk = g_bounds[rr * G2_CNT + g2];
        const int hs = (int)(pk & 0xFF);
        const int he = (int)((pk >> 8) & 0xFF);
        const int ws = (int)((pk >> 16) & 0xFF);
        const int we = (int)(pk >> 24);

        const int oe  = we - 1;
        const int os  = ws - 1;
        const bool zwe = (we == 0);
        const bool zws = (ws == 0);

        const float a00 = zwe ? 0.f : A[he * S_STRIDE + oe];
        const float a01 = zwe ? 0.f : A[hs * S_STRIDE + oe];
        const float a10 = zws ? 0.f : A[he * S_STRIDE + os];
        const float a11 = zws ? 0.f : A[hs * S_STRIDE + os];

        const float b00 = zwe ? 0.f : B[he * S_STRIDE + oe];
        const float b01 = zwe ? 0.f : B[hs * S_STRIDE + oe];
        const float b10 = zws ? 0.f : B[he * S_STRIDE + os];
        const float b11 = zws ? 0.f : B[hs * S_STRIDE + os];

        const float sA = ((a00 - a01) - a10) + a11;
        const float sB = ((b00 - b01) - b10) + b11;

        const int area = (he - hs) * (we - ws);
        const float inv_area = 1.0f / fmaxf((float)area, 1.0f);
        const bool empty = (area <= 0);

        float* op = out + (size_t)rr * C_CH;
        op[c1] = empty ? 0.f : sA * inv_area;
        op[c2] = empty ? 0.f : sB * inv_area;
    }
}

extern "C" void kernel_launch(void* const* d_in, const int* in_sizes, int n_in,
                              void* d_out, int out_size) {
    const float* feature = (const float*)d_in[0];   // (8, 490, 64, 64) fp32
    const float* rois    = (const float*)d_in[1];   // (2000, 5) fp32
    float* out = (float*)d_out;                     // (2000, 10, 7, 7) fp32

    const int bounds_blocks = (R_ROIS * G2_CNT + 255) / 256;   // 383
    prep_kernel<<<1 + bounds_blocks, 256>>>(rois);
    fused_kernel<<<N_BATCH * G2_CNT * (D_OUT / 2), 128>>>(feature, out);
}